// round 6
// baseline (speedup 1.0000x reference)
#include <cuda_runtime.h>
#include <cstdint>
#include <cstddef>

#define T_STEPS 512
#define BATCH   64
#define EMBED   512
#define HIDDEN  1024
#define G4      4096           // 4*HIDDEN gate rows
#define NCLS    10
#define NCTA    128            // persistent grid size (<= 148 SMs, co-resident)
#define WSLD    68             // precompute W-tile smem pad
#define WS2     36             // persistent W-tile smem pad (multiple of 4 for float4)

// ---------------- device-global state (no allocations allowed) ----------------
__device__ float g_X0[(size_t)T_STEPS * G4 * BATCH];   // b0 + x-part of layer0 gates, [t][r][b]
__device__ float g_h0buf[2][HIDDEN * BATCH];           // ping-pong, [k][b]
__device__ float g_h1buf[2][HIDDEN * BATCH];
__device__ float g_c0[HIDDEN * BATCH];
__device__ float g_c1[HIDDEN * BATCH];
__device__ unsigned g_count;                           // monotonic grid-barrier counter

// ---------------- packed fp32x2 FMA (bit-identical to 2x scalar FFMA) ----------------
__device__ __forceinline__ float2 ffma2(float2 a, float2 b, float2 c) {
    unsigned long long ua = *reinterpret_cast<unsigned long long*>(&a);
    unsigned long long ub = *reinterpret_cast<unsigned long long*>(&b);
    unsigned long long uc = *reinterpret_cast<unsigned long long*>(&c);
    asm("fma.rn.f32x2 %0, %1, %2, %0;" : "+l"(uc) : "l"(ua), "l"(ub));
    return *reinterpret_cast<float2*>(&uc);
}

__device__ __forceinline__ float sigf(float v) { return 1.0f / (1.0f + expf(-v)); }

// ---------------- grid barrier: monotonic counter, release/acquire fences ----------------
__device__ __forceinline__ void grid_bar(unsigned target) {
    __threadfence();                       // release: my stores visible at L2
    __syncthreads();
    if (threadIdx.x == 0) {
        atomicAdd(&g_count, 1u);
        while (atomicAdd(&g_count, 0u) < target) { __nanosleep(64); }
    }
    __syncthreads();
    __threadfence();                       // acquire + L1D invalidate (CCTL.IVALL)
}

// =====================================================================
// Precompute X0[t][r][b] = b0[r] + sum_e emb[x[b][t]][e] * W0[r][e]
// grid (T_STEPS, 64 row-tiles), 128 threads; CTA tile 64 rows x 64 batch
// =====================================================================
__global__ __launch_bounds__(128) void precompute_x0(
    const int* __restrict__ x, const float* __restrict__ emb,
    const float* __restrict__ W0, const float* __restrict__ b0)
{
    __shared__ float Hs[32 * 64];     // embedding tile [kk][b]
    __shared__ float Ws[32 * WSLD];   // W tile transposed [kk][r]
    __shared__ int   sidx[64];

    const int tid   = threadIdx.x;
    const int t     = blockIdx.x;
    const int rbase = blockIdx.y * 64;

    if (tid < 64) sidx[tid] = x[tid * T_STEPS + t];
    __syncthreads();

    const int tb   = tid & 7;    // 8 batch-groups of 8
    const int tr   = tid >> 3;   // 16 row-groups of 4
    const int ldrr = tid >> 1;   // staging: row 0..63
    const int ldk0 = (tid & 1) * 16;
    const int eb   = tid >> 1;   // staging: batch 0..63
    const int ek0  = (tid & 1) * 16;

    float2 acc[4][4];
#pragma unroll
    for (int r = 0; r < 4; r++)
#pragma unroll
        for (int p = 0; p < 4; p++) acc[r][p] = make_float2(0.f, 0.f);

    const float* wbase = W0 + (size_t)(rbase + ldrr) * (EMBED + HIDDEN) + ldk0;
    const float* ebase = emb + (size_t)sidx[eb] * EMBED + ek0;

    for (int kt = 0; kt < EMBED; kt += 32) {
#pragma unroll
        for (int i = 0; i < 4; i++) {            // embedding gather -> Hs[kk][b]
            float4 v = *(const float4*)(ebase + kt + i * 4);
            Hs[(ek0 + i * 4 + 0) * 64 + eb] = v.x;
            Hs[(ek0 + i * 4 + 1) * 64 + eb] = v.y;
            Hs[(ek0 + i * 4 + 2) * 64 + eb] = v.z;
            Hs[(ek0 + i * 4 + 3) * 64 + eb] = v.w;
        }
#pragma unroll
        for (int i = 0; i < 4; i++) {            // W -> Ws[kk][r]
            float4 v = *(const float4*)(wbase + kt + i * 4);
            Ws[(ldk0 + i * 4 + 0) * WSLD + ldrr] = v.x;
            Ws[(ldk0 + i * 4 + 1) * WSLD + ldrr] = v.y;
            Ws[(ldk0 + i * 4 + 2) * WSLD + ldrr] = v.z;
            Ws[(ldk0 + i * 4 + 3) * WSLD + ldrr] = v.w;
        }
        __syncthreads();
#pragma unroll 8
        for (int kk = 0; kk < 32; kk++) {
            float4 wv = *(const float4*)&Ws[kk * WSLD + tr * 4];
            float4 ha = *(const float4*)&Hs[kk * 64 + tb * 8];
            float4 hb = *(const float4*)&Hs[kk * 64 + tb * 8 + 4];
            float2 h2[4] = { {ha.x, ha.y}, {ha.z, ha.w}, {hb.x, hb.y}, {hb.z, hb.w} };
            float  wr[4] = { wv.x, wv.y, wv.z, wv.w };
#pragma unroll
            for (int r = 0; r < 4; r++) {
                float2 w2 = make_float2(wr[r], wr[r]);
#pragma unroll
                for (int p = 0; p < 4; p++) acc[r][p] = ffma2(h2[p], w2, acc[r][p]);
            }
        }
        __syncthreads();
    }

#pragma unroll
    for (int r = 0; r < 4; r++) {
        int row = rbase + tr * 4 + r;
        float bb = b0[row];
        float* o = g_X0 + ((size_t)t * G4 + row) * BATCH + tb * 8;
        *(float4*)o       = make_float4(acc[r][0].x + bb, acc[r][0].y + bb,
                                        acc[r][1].x + bb, acc[r][1].y + bb);
        *(float4*)(o + 4) = make_float4(acc[r][2].x + bb, acc[r][2].y + bb,
                                        acc[r][3].x + bb, acc[r][3].y + bb);
    }
}

// =====================================================================
// Persistent recurrence kernel building blocks
// =====================================================================

// One intra-CTA K-half of a 32x64 gate GEMM. 128 threads, thread tile 4r x 4b.
// Staged W rows rr = q*8 + i  <->  global rows q*HIDDEN + cbase + i.
template<int KTILES>
__device__ __forceinline__ void gemm_accum(
    const float* __restrict__ W, int ldw, int wkoff,
    const float* __restrict__ Hsrc, int cbase,
    float* Hs, float* Ws, float2 (&acc)[4][2], int tid128)
{
    const int tb   = tid128 & 15;        // 16 batch groups of 4
    const int tr   = tid128 >> 4;        // 8 row groups of 4
    const int ldrr = tid128 >> 2;        // staged row 0..31
    const int ldk0 = (tid128 & 3) * 8;   // 8 k per thread

    const float* wp = W + (size_t)((ldrr >> 3) * HIDDEN + cbase + (ldrr & 7)) * ldw
                        + wkoff + ldk0;

    for (int kt = 0; kt < KTILES * 32; kt += 32) {
        // global loads first (overlap with previous tile's tail)
        float4 h0r = *(const float4*)&Hsrc[kt * 64 +    0 + tid128 * 4];
        float4 h1r = *(const float4*)&Hsrc[kt * 64 +  512 + tid128 * 4];
        float4 h2r = *(const float4*)&Hsrc[kt * 64 + 1024 + tid128 * 4];
        float4 h3r = *(const float4*)&Hsrc[kt * 64 + 1536 + tid128 * 4];
        float4 wa  = *(const float4*)(wp + kt);
        float4 wb  = *(const float4*)(wp + kt + 4);
        __syncthreads();                 // previous tile fully consumed
        *(float4*)&Hs[   0 + tid128 * 4] = h0r;
        *(float4*)&Hs[ 512 + tid128 * 4] = h1r;
        *(float4*)&Hs[1024 + tid128 * 4] = h2r;
        *(float4*)&Hs[1536 + tid128 * 4] = h3r;
        Ws[(ldk0 + 0) * WS2 + ldrr] = wa.x;
        Ws[(ldk0 + 1) * WS2 + ldrr] = wa.y;
        Ws[(ldk0 + 2) * WS2 + ldrr] = wa.z;
        Ws[(ldk0 + 3) * WS2 + ldrr] = wa.w;
        Ws[(ldk0 + 4) * WS2 + ldrr] = wb.x;
        Ws[(ldk0 + 5) * WS2 + ldrr] = wb.y;
        Ws[(ldk0 + 6) * WS2 + ldrr] = wb.z;
        Ws[(ldk0 + 7) * WS2 + ldrr] = wb.w;
        __syncthreads();
#pragma unroll 8
        for (int kk = 0; kk < 32; kk++) {
            float4 wv = *(const float4*)&Ws[kk * WS2 + tr * 4];
            float4 hv = *(const float4*)&Hs[kk * 64 + tb * 4];
            float2 hA = make_float2(hv.x, hv.y);
            float2 hB = make_float2(hv.z, hv.w);
            float  wr[4] = { wv.x, wv.y, wv.z, wv.w };
#pragma unroll
            for (int r = 0; r < 4; r++) {
                float2 w2 = make_float2(wr[r], wr[r]);
                acc[r][0] = ffma2(hA, w2, acc[r][0]);
                acc[r][1] = ffma2(hB, w2, acc[r][1]);
            }
        }
    }
}

// Combine the two K-halves' partials into red[32][64] (complete gates).
__device__ __forceinline__ void reduce_gates(float2 (&acc)[4][2], float* red,
                                             int hh, int tid128)
{
    const int tb = tid128 & 15;
    const int tr = tid128 >> 4;
    __syncthreads();                     // all compute done (smem reuse safe)
    if (hh == 1) {
#pragma unroll
        for (int r = 0; r < 4; r++) {
            *(float2*)&red[(tr * 4 + r) * 64 + tb * 4]     = acc[r][0];
            *(float2*)&red[(tr * 4 + r) * 64 + tb * 4 + 2] = acc[r][1];
        }
    }
    __syncthreads();
    if (hh == 0) {
#pragma unroll
        for (int r = 0; r < 4; r++) {
            float2* p = (float2*)&red[(tr * 4 + r) * 64 + tb * 4];
            float2 v0 = p[0], v1 = p[1];
            v0.x += acc[r][0].x; v0.y += acc[r][0].y;
            v1.x += acc[r][1].x; v1.y += acc[r][1].y;
            p[0] = v0; p[1] = v1;
        }
    }
    __syncthreads();
}

// Fused LSTM cell update for this CTA's 8 hidden units x 64 batch.
// x0t != nullptr: layer0 (gates += X0[t], bias already folded in).
// else: gates += bias[r] (layer1).
__device__ __forceinline__ void cell_update(const float* red, const float* x0t,
                                            const float* __restrict__ bias,
                                            float* cst, float* hout, int cbase)
{
#pragma unroll
    for (int u = 0; u < 2; u++) {
        int cell = threadIdx.x + u * 256;   // 0..511 coalesced
        int jl = cell >> 6, b = cell & 63;
        float g[4];
#pragma unroll
        for (int q = 0; q < 4; q++) {
            float v = red[(q * 8 + jl) * 64 + b];
            if (x0t) v += x0t[(size_t)(q * HIDDEN + cbase + jl) * BATCH + b];
            else     v += bias[q * HIDDEN + cbase + jl];
            g[q] = v;
        }
        int gidx = (cbase + jl) * BATCH + b;
        float c  = cst[gidx];
        float cn = sigf(g[1]) * c + sigf(g[0]) * tanhf(g[2]);
        cst[gidx]  = cn;
        hout[gidx] = sigf(g[3]) * tanhf(cn);
    }
}

// =====================================================================
// The persistent kernel: full 512-step recurrence, 2 grid barriers/step.
// CTA c owns hidden units [c*8, c*8+8) for BOTH layers.
// =====================================================================
__global__ __launch_bounds__(256, 1) void lstm_persistent(
    const float* __restrict__ W0, const float* __restrict__ W1,
    const float* __restrict__ b1)
{
    __shared__ float Hs0[2048], Ws0[32 * WS2];
    __shared__ float Hs1[2048], Ws1[32 * WS2];
    __shared__ float red[2048];

    const int tid    = threadIdx.x;
    const int hh     = tid >> 7;           // intra-CTA K-half
    const int tid128 = tid & 127;
    const int cbase  = blockIdx.x * 8;     // first hidden unit owned
    float* Hs = hh ? Hs1 : Hs0;
    float* Ws = hh ? Ws1 : Ws0;

    unsigned bars = 0;

    for (int t = 0; t < T_STEPS; t++) {
        const int p = t & 1;

        // ---- layer 0: gates = X0[t] + W0[:, E:E+H] @ h0_old ----
        float2 acc[4][2];
#pragma unroll
        for (int r = 0; r < 4; r++) { acc[r][0] = make_float2(0.f, 0.f);
                                      acc[r][1] = make_float2(0.f, 0.f); }
        gemm_accum<16>(W0, EMBED + HIDDEN, EMBED + hh * 512,
                       g_h0buf[p] + hh * 512 * BATCH, cbase, Hs, Ws, acc, tid128);
        reduce_gates(acc, red, hh, tid128);
        cell_update(red, g_X0 + (size_t)t * G4 * BATCH, nullptr,
                    g_c0, g_h0buf[p ^ 1], cbase);
        bars++; grid_bar(bars * NCTA);     // h0_new complete everywhere

        // ---- layer 1: gates = b1 + W1 @ [h0_new ; h1_old] ----
#pragma unroll
        for (int r = 0; r < 4; r++) { acc[r][0] = make_float2(0.f, 0.f);
                                      acc[r][1] = make_float2(0.f, 0.f); }
        gemm_accum<32>(W1, 2 * HIDDEN, hh * 1024,
                       hh ? g_h1buf[p] : g_h0buf[p ^ 1], cbase, Hs, Ws, acc, tid128);
        reduce_gates(acc, red, hh, tid128);
        cell_update(red, nullptr, b1, g_c1, g_h1buf[p ^ 1], cbase);
        bars++; grid_bar(bars * NCTA);     // h1_new complete everywhere
    }
}

// =====================================================================
// Final classifier: out[b][c] = bV[c] + sum_j h1[j][b] * V[c][j]
// (final h1 lives in g_h1buf[0]: last write at t=511 -> buf[(511&1)^1] = 0)
// =====================================================================
__global__ void classify(const float* __restrict__ V, const float* __restrict__ bV,
                         float* __restrict__ out)
{
    int c = blockIdx.x;     // 10 blocks
    int b = threadIdx.x;    // 64 threads
    const float* vr = V + (size_t)c * HIDDEN;
    float a = bV[c];
#pragma unroll 4
    for (int j = 0; j < HIDDEN; j++)
        a += g_h1buf[0][j * BATCH + b] * vr[j];
    out[b * NCLS + c] = a;
}

__global__ void zero_state()
{
    int i = blockIdx.x * 1024 + threadIdx.x;      // 64 blocks x 1024 = 65536
    g_h0buf[0][i] = 0.f; g_h0buf[1][i] = 0.f;
    g_h1buf[0][i] = 0.f; g_h1buf[1][i] = 0.f;
    g_c0[i] = 0.f; g_c1[i] = 0.f;
    if (i == 0) g_count = 0u;
}

// =====================================================================
extern "C" void kernel_launch(void* const* d_in, const int* in_sizes, int n_in,
                              void* d_out, int out_size)
{
    (void)in_sizes; (void)n_in; (void)out_size;
    const int*   x   = (const int*)d_in[0];
    const float* emb = (const float*)d_in[1];
    const float* W0  = (const float*)d_in[2];
    const float* b0  = (const float*)d_in[3];
    const float* W1  = (const float*)d_in[4];
    const float* b1  = (const float*)d_in[5];
    const float* V   = (const float*)d_in[6];
    const float* bV  = (const float*)d_in[7];
    float* out = (float*)d_out;

    zero_state<<<64, 1024>>>();
    precompute_x0<<<dim3(T_STEPS, 64), 128>>>(x, emb, W0, b0);
    lstm_persistent<<<NCTA, 256>>>(W0, W1, b1);
    classify<<<NCLS, BATCH>>>(V, bV, out);
}

// round 7
// speedup vs baseline: 1.2202x; 1.2202x over previous
#include <cuda_runtime.h>
#include <cstdint>
#include <cstddef>

#define T_STEPS 512
#define BATCH   64
#define EMBED   512
#define HIDDEN  1024
#define G4      4096           // 4*HIDDEN gate rows
#define NCLS    10
#define NCTA    128            // persistent grid (<=148 SMs, co-resident)
#define WSLD    68             // precompute W-tile smem pad
#define WS2     36             // persistent W-tile smem pad (mult of 4 for float4)

#define HS_FLOATS (4 * 2048)                 // 4 group H tiles (alias: gate partials)
#define WS_FLOATS (4 * 32 * WS2)             // 4 group W tiles
#define SMEM_BYTES ((HS_FLOATS + WS_FLOATS) * 4)

// ---------------- device-global state (no allocations allowed) ----------------
__device__ float g_X0[(size_t)T_STEPS * G4 * BATCH];   // b0 + x-part of layer0 gates, [t][r][b]
__device__ float g_h0buf[2][HIDDEN * BATCH];           // ping-pong, [k][b]
__device__ float g_h1buf[2][HIDDEN * BATCH];
__device__ unsigned g_cA, g_cB;                        // monotonic barrier counters

// ---------------- packed fp32x2 FMA (bit-identical to 2x scalar FFMA) ----------------
__device__ __forceinline__ float2 ffma2(float2 a, float2 b, float2 c) {
    unsigned long long ua = *reinterpret_cast<unsigned long long*>(&a);
    unsigned long long ub = *reinterpret_cast<unsigned long long*>(&b);
    unsigned long long uc = *reinterpret_cast<unsigned long long*>(&c);
    asm("fma.rn.f32x2 %0, %1, %2, %0;" : "+l"(uc) : "l"(ua), "l"(ub));
    return *reinterpret_cast<float2*>(&uc);
}

__device__ __forceinline__ float sigf(float v) { return 1.0f / (1.0f + expf(-v)); }

__device__ __forceinline__ void barg(int g) {
    asm volatile("bar.sync %0, 128;" :: "r"(g + 1) : "memory");
}

// Elected-lane spin on a monotonic counter, then group barrier.
// __threadfence() after the observation = acquire + L1D invalidate (CCTL.IVALL).
__device__ __forceinline__ void group_wait(unsigned* ctr, unsigned target, int g, int tg) {
    if (tg == 0) {
        while (*(volatile unsigned*)ctr < target) { __nanosleep(32); }
        __threadfence();
    }
    barg(g);
}

// =====================================================================
// Precompute X0[t][r][b] = b0[r] + sum_e emb[x[b][t]][e] * W0[r][e]
// grid (T_STEPS, 64 row-tiles), 128 threads; CTA tile 64 rows x 64 batch
// =====================================================================
__global__ __launch_bounds__(128) void precompute_x0(
    const int* __restrict__ x, const float* __restrict__ emb,
    const float* __restrict__ W0, const float* __restrict__ b0)
{
    __shared__ float Hs[32 * 64];     // embedding tile [kk][b]
    __shared__ float Ws[32 * WSLD];   // W tile transposed [kk][r]
    __shared__ int   sidx[64];

    const int tid   = threadIdx.x;
    const int t     = blockIdx.x;
    const int rbase = blockIdx.y * 64;

    if (tid < 64) sidx[tid] = x[tid * T_STEPS + t];
    __syncthreads();

    const int tb   = tid & 7;
    const int tr   = tid >> 3;
    const int ldrr = tid >> 1;
    const int ldk0 = (tid & 1) * 16;
    const int eb   = tid >> 1;
    const int ek0  = (tid & 1) * 16;

    float2 acc[4][4];
#pragma unroll
    for (int r = 0; r < 4; r++)
#pragma unroll
        for (int p = 0; p < 4; p++) acc[r][p] = make_float2(0.f, 0.f);

    const float* wbase = W0 + (size_t)(rbase + ldrr) * (EMBED + HIDDEN) + ldk0;
    const float* ebase = emb + (size_t)sidx[eb] * EMBED + ek0;

    for (int kt = 0; kt < EMBED; kt += 32) {
#pragma unroll
        for (int i = 0; i < 4; i++) {
            float4 v = *(const float4*)(ebase + kt + i * 4);
            Hs[(ek0 + i * 4 + 0) * 64 + eb] = v.x;
            Hs[(ek0 + i * 4 + 1) * 64 + eb] = v.y;
            Hs[(ek0 + i * 4 + 2) * 64 + eb] = v.z;
            Hs[(ek0 + i * 4 + 3) * 64 + eb] = v.w;
        }
#pragma unroll
        for (int i = 0; i < 4; i++) {
            float4 v = *(const float4*)(wbase + kt + i * 4);
            Ws[(ldk0 + i * 4 + 0) * WSLD + ldrr] = v.x;
            Ws[(ldk0 + i * 4 + 1) * WSLD + ldrr] = v.y;
            Ws[(ldk0 + i * 4 + 2) * WSLD + ldrr] = v.z;
            Ws[(ldk0 + i * 4 + 3) * WSLD + ldrr] = v.w;
        }
        __syncthreads();
#pragma unroll 8
        for (int kk = 0; kk < 32; kk++) {
            float4 wv = *(const float4*)&Ws[kk * WSLD + tr * 4];
            float4 ha = *(const float4*)&Hs[kk * 64 + tb * 8];
            float4 hb = *(const float4*)&Hs[kk * 64 + tb * 8 + 4];
            float2 h2[4] = { {ha.x, ha.y}, {ha.z, ha.w}, {hb.x, hb.y}, {hb.z, hb.w} };
            float  wr[4] = { wv.x, wv.y, wv.z, wv.w };
#pragma unroll
            for (int r = 0; r < 4; r++) {
                float2 w2 = make_float2(wr[r], wr[r]);
#pragma unroll
                for (int p = 0; p < 4; p++) acc[r][p] = ffma2(h2[p], w2, acc[r][p]);
            }
        }
        __syncthreads();
    }

#pragma unroll
    for (int r = 0; r < 4; r++) {
        int row = rbase + tr * 4 + r;
        float bb = b0[row];
        float* o = g_X0 + ((size_t)t * G4 + row) * BATCH + tb * 8;
        *(float4*)o       = make_float4(acc[r][0].x + bb, acc[r][0].y + bb,
                                        acc[r][1].x + bb, acc[r][1].y + bb);
        *(float4*)(o + 4) = make_float4(acc[r][2].x + bb, acc[r][2].y + bb,
                                        acc[r][3].x + bb, acc[r][3].y + bb);
    }
}

// =====================================================================
// Per-group GEMM: 32 gate rows x 64 batch, group-local K range, register-
// pipelined tiles (load k+1 while computing k), group-local named barriers.
// Staged row rr = q*8 + i  <->  global gate row q*HIDDEN + cbase + i.
// =====================================================================
template<int KTILES>
__device__ __forceinline__ void gemm_group(
    const float* __restrict__ W, int ldw, int wkoff,
    const float* __restrict__ Hsrc, int cbase, int g, int tg,
    float* Hs, float* Ws, float2 (&acc)[4][2])
{
    const int tb   = tg & 15;        // 16 batch groups of 4
    const int tr   = tg >> 4;        // 8 row groups of 4
    const int ldrr = tg >> 2;        // staged row 0..31
    const int ldk0 = (tg & 3) * 8;   // 8 k per thread

    const float* wp = W + (size_t)((ldrr >> 3) * HIDDEN + cbase + (ldrr & 7)) * ldw
                        + wkoff + ldk0;

    // preload tile 0
    float4 h0r = *(const float4*)&Hsrc[   0 + tg * 4];
    float4 h1r = *(const float4*)&Hsrc[ 512 + tg * 4];
    float4 h2r = *(const float4*)&Hsrc[1024 + tg * 4];
    float4 h3r = *(const float4*)&Hsrc[1536 + tg * 4];
    float4 wa  = *(const float4*)(wp);
    float4 wb  = *(const float4*)(wp + 4);

    for (int kt = 0; kt < KTILES; kt++) {
        barg(g);                     // previous tile fully consumed by this group
        *(float4*)&Hs[   0 + tg * 4] = h0r;
        *(float4*)&Hs[ 512 + tg * 4] = h1r;
        *(float4*)&Hs[1024 + tg * 4] = h2r;
        *(float4*)&Hs[1536 + tg * 4] = h3r;
        Ws[(ldk0 + 0) * WS2 + ldrr] = wa.x;
        Ws[(ldk0 + 1) * WS2 + ldrr] = wa.y;
        Ws[(ldk0 + 2) * WS2 + ldrr] = wa.z;
        Ws[(ldk0 + 3) * WS2 + ldrr] = wa.w;
        Ws[(ldk0 + 4) * WS2 + ldrr] = wb.x;
        Ws[(ldk0 + 5) * WS2 + ldrr] = wb.y;
        Ws[(ldk0 + 6) * WS2 + ldrr] = wb.z;
        Ws[(ldk0 + 7) * WS2 + ldrr] = wb.w;
        barg(g);
        if (kt + 1 < KTILES) {       // prefetch next tile (latency hidden by compute)
            const float* hn = Hsrc + (kt + 1) * 2048;
            h0r = *(const float4*)&hn[   0 + tg * 4];
            h1r = *(const float4*)&hn[ 512 + tg * 4];
            h2r = *(const float4*)&hn[1024 + tg * 4];
            h3r = *(const float4*)&hn[1536 + tg * 4];
            wa  = *(const float4*)(wp + (kt + 1) * 32);
            wb  = *(const float4*)(wp + (kt + 1) * 32 + 4);
        }
#pragma unroll 8
        for (int kk = 0; kk < 32; kk++) {
            float4 wv = *(const float4*)&Ws[kk * WS2 + tr * 4];
            float4 hv = *(const float4*)&Hs[kk * 64 + tb * 4];
            float2 hA = make_float2(hv.x, hv.y);
            float2 hB = make_float2(hv.z, hv.w);
            float  wr[4] = { wv.x, wv.y, wv.z, wv.w };
#pragma unroll
            for (int r = 0; r < 4; r++) {
                float2 w2 = make_float2(wr[r], wr[r]);
                acc[r][0] = ffma2(hA, w2, acc[r][0]);
                acc[r][1] = ffma2(hB, w2, acc[r][1]);
            }
        }
    }
}

// Write this group's partial tile into its (now free) Hs buffer.
__device__ __forceinline__ void write_partial(float2 (&acc)[4][2], float* Hs,
                                              int g, int tg)
{
    const int tb = tg & 15;
    const int tr = tg >> 4;
    barg(g);                         // group's compute done; Hs reusable
#pragma unroll
    for (int r = 0; r < 4; r++) {
        *(float2*)&Hs[(tr * 4 + r) * 64 + tb * 4]     = acc[r][0];
        *(float2*)&Hs[(tr * 4 + r) * 64 + tb * 4 + 2] = acc[r][1];
    }
}

// =====================================================================
// Persistent kernel: CTA c owns hidden units [c*8, c*8+8) for BOTH layers.
// 512 threads = 4 K-groups of 128. c-state lives in registers for all steps.
// =====================================================================
__global__ __launch_bounds__(512, 1) void lstm_persistent(
    const float* __restrict__ W0, const float* __restrict__ W1,
    const float* __restrict__ b1)
{
    extern __shared__ float dsm[];
    float* HsA = dsm;                 // [4][2048] H tiles, aliased as gate partials
    float* WsA = dsm + HS_FLOATS;     // [4][32*WS2]

    const int tid   = threadIdx.x;
    const int g     = tid >> 7;
    const int tg    = tid & 127;
    const int cbase = blockIdx.x * 8;
    const int jl    = tid >> 6;       // 0..7 local hidden unit
    const int b     = tid & 63;       // batch lane
    float* Hs = HsA + g * 2048;
    float* Ws = WsA + g * (32 * WS2);

    float c0 = 0.f, c1 = 0.f;         // exclusive cell state, register-resident
    float b1r[4];
#pragma unroll
    for (int q = 0; q < 4; q++) b1r[q] = b1[q * HIDDEN + cbase + jl];

    for (int t = 0; t < T_STEPS; t++) {
        const int p = t & 1;
        const float* h0_old = g_h0buf[p];
        float*       h0_new = g_h0buf[p ^ 1];
        const float* h1_old = g_h1buf[p];
        float*       h1_new = g_h1buf[p ^ 1];

        // prefetch this thread's X0 gate values (DRAM latency hides under GEMM)
        const float* X0t = g_X0 + (size_t)t * G4 * BATCH;
        float x0r[4];
#pragma unroll
        for (int q = 0; q < 4; q++)
            x0r[q] = X0t[(size_t)(q * HIDDEN + cbase + jl) * BATCH + b];

        // ---- layer 0: gates = X0[t] + W0[:, E:E+H] @ h0_old ----
        float2 acc[4][2];
#pragma unroll
        for (int r = 0; r < 4; r++) { acc[r][0] = make_float2(0.f, 0.f);
                                      acc[r][1] = make_float2(0.f, 0.f); }
        gemm_group<8>(W0, EMBED + HIDDEN, EMBED + g * 256,
                      h0_old + g * 256 * BATCH, cbase, g, tg, Hs, Ws, acc);
        write_partial(acc, Hs, g, tg);
        __syncthreads();
        {
            float gs[4];
#pragma unroll
            for (int q = 0; q < 4; q++) {
                float v = x0r[q];
#pragma unroll
                for (int gg = 0; gg < 4; gg++)
                    v += HsA[gg * 2048 + (q * 8 + jl) * 64 + b];
                gs[q] = v;
            }
            float cn = sigf(gs[1]) * c0 + sigf(gs[0]) * tanhf(gs[2]);
            c0 = cn;
            h0_new[(cbase + jl) * BATCH + b] = sigf(gs[3]) * tanhf(cn);
        }
        __syncthreads();
        if (tid == 0) { __threadfence(); atomicAdd(&g_cA, 1u); }

        // ---- layer 1: gates = b1 + W1 @ [h0_new ; h1_old] ----
        // groups 2,3 (h1_old half) start immediately; groups 0,1 wait for h0_new.
#pragma unroll
        for (int r = 0; r < 4; r++) { acc[r][0] = make_float2(0.f, 0.f);
                                      acc[r][1] = make_float2(0.f, 0.f); }
        if (g < 2) {
            group_wait(&g_cA, (unsigned)(t + 1) * NCTA, g, tg);
            gemm_group<16>(W1, 2 * HIDDEN, g * 512,
                           h0_new + g * 512 * BATCH, cbase, g, tg, Hs, Ws, acc);
        } else {
            group_wait(&g_cB, (unsigned)t * NCTA, g, tg);
            gemm_group<16>(W1, 2 * HIDDEN, g * 512,
                           h1_old + (g - 2) * 512 * BATCH, cbase, g, tg, Hs, Ws, acc);
        }
        write_partial(acc, Hs, g, tg);
        __syncthreads();
        {
            float gs[4];
#pragma unroll
            for (int q = 0; q < 4; q++) {
                float v = b1r[q];
#pragma unroll
                for (int gg = 0; gg < 4; gg++)
                    v += HsA[gg * 2048 + (q * 8 + jl) * 64 + b];
                gs[q] = v;
            }
            float cn = sigf(gs[1]) * c1 + sigf(gs[0]) * tanhf(gs[2]);
            c1 = cn;
            h1_new[(cbase + jl) * BATCH + b] = sigf(gs[3]) * tanhf(cn);
        }
        __syncthreads();
        if (tid == 0) { __threadfence(); atomicAdd(&g_cB, 1u); }
    }
}

// =====================================================================
// Classifier: out[b][c] = bV[c] + sum_j h1[j][b] * V[c][j]
// (final h1 is g_h1buf[0]: last write at t=511 -> buf[(511&1)^1] = 0)
// grid 10 (one per class), 512 threads, j split 8 ways + smem reduce.
// =====================================================================
__global__ __launch_bounds__(512) void classify(
    const float* __restrict__ V, const float* __restrict__ bV,
    float* __restrict__ out)
{
    __shared__ float red[512];
    const int c  = blockIdx.x;
    const int tid = threadIdx.x;
    const int b  = tid & 63;
    const int sl = tid >> 6;          // j-slice 0..7
    const float* vr = V + (size_t)c * HIDDEN + sl * 128;
    const float* hp = g_h1buf[0] + (size_t)sl * 128 * BATCH + b;
    float a = 0.f;
#pragma unroll 8
    for (int j = 0; j < 128; j++) a += hp[j * BATCH] * vr[j];
    red[tid] = a;
    __syncthreads();
    if (tid < 64) {
        float s = bV[c];
#pragma unroll
        for (int k = 0; k < 8; k++) s += red[k * 64 + tid];
        out[tid * NCLS + c] = s;
    }
}

__global__ void zero_state()
{
    int i = blockIdx.x * 1024 + threadIdx.x;      // 64 x 1024 = 65536
    g_h0buf[0][i] = 0.f; g_h0buf[1][i] = 0.f;
    g_h1buf[0][i] = 0.f; g_h1buf[1][i] = 0.f;
    if (i == 0) { g_cA = 0u; g_cB = 0u; }
}

// =====================================================================
extern "C" void kernel_launch(void* const* d_in, const int* in_sizes, int n_in,
                              void* d_out, int out_size)
{
    (void)in_sizes; (void)n_in; (void)out_size;
    const int*   x   = (const int*)d_in[0];
    const float* emb = (const float*)d_in[1];
    const float* W0  = (const float*)d_in[2];
    const float* b0  = (const float*)d_in[3];
    const float* W1  = (const float*)d_in[4];
    const float* b1  = (const float*)d_in[5];
    const float* V   = (const float*)d_in[6];
    const float* bV  = (const float*)d_in[7];
    float* out = (float*)d_out;

    cudaFuncSetAttribute(lstm_persistent,
                         cudaFuncAttributeMaxDynamicSharedMemorySize, SMEM_BYTES);

    zero_state<<<64, 1024>>>();
    precompute_x0<<<dim3(T_STEPS, 64), 128>>>(x, emb, W0, b0);
    lstm_persistent<<<NCTA, 512, SMEM_BYTES>>>(W0, W1, b1);
    classify<<<NCLS, BATCH * 8>>>(V, bV, out);
}

// round 9
// speedup vs baseline: 1.3447x; 1.1020x over previous
#include <cuda_runtime.h>
#include <cstdint>
#include <cstddef>

#define T_STEPS 512
#define BATCH   64
#define EMBED   512
#define HIDDEN  1024
#define G4      4096           // 4*HIDDEN gate rows
#define NCLS    10
#define NCTA    128            // persistent grid (<=148 SMs, co-resident)
#define WSLD    68             // precompute W-tile smem pad
#define PSTR    34             // partial-tile row stride (EVEN: float2-aligned; pad vs banks)
#define TILE_F  4096           // floats per pair tile (16KB)
#define SMEM_BYTES (8 * TILE_F * 4)   // 128KB: 8 pair W-tiles / partials

// ---------------- device-global state (no allocations allowed) ----------------
__device__ float g_X0[(size_t)T_STEPS * G4 * BATCH];   // b0 + x-part of layer0 gates, [t][r][b]
__device__ float g_h0buf[2][HIDDEN * BATCH];           // ping-pong, [k][b]
__device__ float g_h1buf[2][HIDDEN * BATCH];
__device__ unsigned g_cA, g_cB;                        // monotonic barrier counters

// ---------------- packed fp32x2 FMA (bit-identical to 2x scalar FFMA) ----------------
__device__ __forceinline__ float2 ffma2(float2 a, float2 b, float2 c) {
    unsigned long long ua = *reinterpret_cast<unsigned long long*>(&a);
    unsigned long long ub = *reinterpret_cast<unsigned long long*>(&b);
    unsigned long long uc = *reinterpret_cast<unsigned long long*>(&c);
    asm("fma.rn.f32x2 %0, %1, %2, %0;" : "+l"(uc) : "l"(ua), "l"(ub));
    return *reinterpret_cast<float2*>(&uc);
}

__device__ __forceinline__ float sigf(float v) { return 1.0f / (1.0f + expf(-v)); }

// pair barrier: warps 2s, 2s+1 (64 threads), HW barrier id s+1
__device__ __forceinline__ void barp(int s) {
    asm volatile("bar.sync %0, 64;" :: "r"(s + 1) : "memory");
}

// Elected-lane spin on a monotonic counter + acquire fence, then pair barrier.
__device__ __forceinline__ void ctr_wait(unsigned* ctr, unsigned target, int s, int pt) {
    if (pt == 0) {
        while (*(volatile unsigned*)ctr < target) { __nanosleep(32); }
        __threadfence();                // acquire + CCTL.IVALL (SM-wide L1 inval)
    }
    barp(s);
}

// =====================================================================
// Precompute X0[t][r][b] = b0[r] + sum_e emb[x[b][t]][e] * W0[r][e]
// grid (T_STEPS, 64 row-tiles), 128 threads; CTA tile 64 rows x 64 batch
// =====================================================================
__global__ __launch_bounds__(128) void precompute_x0(
    const int* __restrict__ x, const float* __restrict__ emb,
    const float* __restrict__ W0, const float* __restrict__ b0)
{
    __shared__ float Hs[32 * 64];     // embedding tile [kk][b]
    __shared__ float Ws[32 * WSLD];   // W tile transposed [kk][r]
    __shared__ int   sidx[64];

    const int tid   = threadIdx.x;
    const int t     = blockIdx.x;
    const int rbase = blockIdx.y * 64;

    if (tid < 64) sidx[tid] = x[tid * T_STEPS + t];
    __syncthreads();

    const int tb   = tid & 7;
    const int tr   = tid >> 3;
    const int ldrr = tid >> 1;
    const int ldk0 = (tid & 1) * 16;
    const int eb   = tid >> 1;
    const int ek0  = (tid & 1) * 16;

    float2 acc[4][4];
#pragma unroll
    for (int r = 0; r < 4; r++)
#pragma unroll
        for (int p = 0; p < 4; p++) acc[r][p] = make_float2(0.f, 0.f);

    const float* wbase = W0 + (size_t)(rbase + ldrr) * (EMBED + HIDDEN) + ldk0;
    const float* ebase = emb + (size_t)sidx[eb] * EMBED + ek0;

    for (int kt = 0; kt < EMBED; kt += 32) {
#pragma unroll
        for (int i = 0; i < 4; i++) {
            float4 v = *(const float4*)(ebase + kt + i * 4);
            Hs[(ek0 + i * 4 + 0) * 64 + eb] = v.x;
            Hs[(ek0 + i * 4 + 1) * 64 + eb] = v.y;
            Hs[(ek0 + i * 4 + 2) * 64 + eb] = v.z;
            Hs[(ek0 + i * 4 + 3) * 64 + eb] = v.w;
        }
#pragma unroll
        for (int i = 0; i < 4; i++) {
            float4 v = *(const float4*)(wbase + kt + i * 4);
            Ws[(ldk0 + i * 4 + 0) * WSLD + ldrr] = v.x;
            Ws[(ldk0 + i * 4 + 1) * WSLD + ldrr] = v.y;
            Ws[(ldk0 + i * 4 + 2) * WSLD + ldrr] = v.z;
            Ws[(ldk0 + i * 4 + 3) * WSLD + ldrr] = v.w;
        }
        __syncthreads();
#pragma unroll 8
        for (int kk = 0; kk < 32; kk++) {
            float4 wv = *(const float4*)&Ws[kk * WSLD + tr * 4];
            float4 ha = *(const float4*)&Hs[kk * 64 + tb * 8];
            float4 hb = *(const float4*)&Hs[kk * 64 + tb * 8 + 4];
            float2 h2[4] = { {ha.x, ha.y}, {ha.z, ha.w}, {hb.x, hb.y}, {hb.z, hb.w} };
            float  wr[4] = { wv.x, wv.y, wv.z, wv.w };
#pragma unroll
            for (int r = 0; r < 4; r++) {
                float2 w2 = make_float2(wr[r], wr[r]);
#pragma unroll
                for (int p = 0; p < 4; p++) acc[r][p] = ffma2(h2[p], w2, acc[r][p]);
            }
        }
        __syncthreads();
    }

#pragma unroll
    for (int r = 0; r < 4; r++) {
        int row = rbase + tr * 4 + r;
        float bb = b0[row];
        float* o = g_X0 + ((size_t)t * G4 + row) * BATCH + tb * 8;
        *(float4*)o       = make_float4(acc[r][0].x + bb, acc[r][0].y + bb,
                                        acc[r][1].x + bb, acc[r][1].y + bb);
        *(float4*)(o + 4) = make_float4(acc[r][2].x + bb, acc[r][2].y + bb,
                                        acc[r][3].x + bb, acc[r][3].y + bb);
    }
}

// =====================================================================
// Stage a 32-row x 128-k slice of W into smem, repacked [k][32 rows].
// Pair-cooperative: 64 threads; thread = (row rr = pt&31, k-half kc = pt>>5).
// Staged row rr = q*8+i  <->  global gate row q*HIDDEN + cbase + i.
// =====================================================================
__device__ __forceinline__ void stage_W(
    const float* __restrict__ W, int ldw, int col0, int cbase,
    float* Wt, int pt)
{
    const int rr = pt & 31, kc = pt >> 5;
    const int q = rr >> 3, i = rr & 7;
    const float* src = W + (size_t)(q * HIDDEN + cbase + i) * ldw + col0 + kc * 64;
#pragma unroll
    for (int j = 0; j < 16; j++) {
        float4 v = *(const float4*)(src + j * 4);
        int kl = kc * 64 + j * 4;
        Wt[(kl + 0) * 32 + rr] = v.x;
        Wt[(kl + 1) * 32 + rr] = v.y;
        Wt[(kl + 2) * 32 + rr] = v.z;
        Wt[(kl + 3) * 32 + rr] = v.w;
    }
}

// =====================================================================
// 128-k GEMM chunk: warp tile 32 rows x 32 batch, thread 4r x 8b.
// W from smem [k][32] (1 LDS.128/kk, dedup), H straight from L2
// (2 LDG.128/kk, sector-dedup). Depth-2 register double buffering.
// =====================================================================
__device__ __forceinline__ void gemm128(
    const float* __restrict__ hp,     // hsrc + koff*64 + hf*32 + bg*8
    const float* __restrict__ wp,     // Wt + rg*4
    float2 (&acc)[4][4])
{
    float4 ha0 = *(const float4*)(hp);
    float4 hb0 = *(const float4*)(hp + 4);
    float4 wv0 = *(const float4*)(wp);
    float4 ha1 = *(const float4*)(hp + 64);
    float4 hb1 = *(const float4*)(hp + 68);
    float4 wv1 = *(const float4*)(wp + 32);

#pragma unroll 4
    for (int kl = 0; kl < 128; kl += 2) {
        {   // compute kl (slot 0)
            float2 h2[4] = { {ha0.x,ha0.y},{ha0.z,ha0.w},{hb0.x,hb0.y},{hb0.z,hb0.w} };
            float  wr[4] = { wv0.x, wv0.y, wv0.z, wv0.w };
#pragma unroll
            for (int r = 0; r < 4; r++) {
                float2 w2 = make_float2(wr[r], wr[r]);
#pragma unroll
                for (int j = 0; j < 4; j++) acc[r][j] = ffma2(h2[j], w2, acc[r][j]);
            }
        }
        int kn = (kl + 2 <= 126) ? kl + 2 : 126;      // clamped tail prefetch
        ha0 = *(const float4*)(hp + kn * 64);
        hb0 = *(const float4*)(hp + kn * 64 + 4);
        wv0 = *(const float4*)(wp + kn * 32);
        {   // compute kl+1 (slot 1)
            float2 h2[4] = { {ha1.x,ha1.y},{ha1.z,ha1.w},{hb1.x,hb1.y},{hb1.z,hb1.w} };
            float  wr[4] = { wv1.x, wv1.y, wv1.z, wv1.w };
#pragma unroll
            for (int r = 0; r < 4; r++) {
                float2 w2 = make_float2(wr[r], wr[r]);
#pragma unroll
                for (int j = 0; j < 4; j++) acc[r][j] = ffma2(h2[j], w2, acc[r][j]);
            }
        }
        int km = (kl + 3 <= 127) ? kl + 3 : 127;
        ha1 = *(const float4*)(hp + km * 64);
        hb1 = *(const float4*)(hp + km * 64 + 4);
        wv1 = *(const float4*)(wp + km * 32);
    }
}

// Write the warp's 32x32 partial into its own tile slice (padded EVEN stride).
__device__ __forceinline__ void write_partial(float2 (&acc)[4][4], float* part,
                                              int rg, int bg)
{
#pragma unroll
    for (int r = 0; r < 4; r++) {
        float* row = part + (rg * 4 + r) * PSTR + bg * 8;
#pragma unroll
        for (int j = 0; j < 4; j++) *(float2*)(row + j * 2) = acc[r][j];
    }
}

// =====================================================================
// Persistent kernel: CTA owns 8 hidden units (32 gate rows) for BOTH layers.
// 512 threads = 16 warps = 8 K-splits x 2 batch-halves.
// =====================================================================
__global__ __launch_bounds__(512, 1) void lstm_persistent(
    const float* __restrict__ W0, const float* __restrict__ W1,
    const float* __restrict__ b1)
{
    extern __shared__ float dsm[];    // 8 pair tiles of TILE_F floats

    const int tid   = threadIdx.x;
    const int w     = tid >> 5;
    const int lane  = tid & 31;
    const int s     = w >> 1;         // K-split 0..7
    const int hf    = w & 1;          // batch half
    const int pt    = tid & 63;       // pair-local thread
    const int rg    = lane >> 2;      // row group (4 rows)
    const int bg    = lane & 3;       // batch group (8 batch)
    const int cbase = blockIdx.x * 8;
    const int jl    = tid >> 6;       // cell phase: local hidden unit 0..7
    const int b     = tid & 63;       // cell phase: batch lane

    float* Wt   = dsm + s * TILE_F;
    float* part = Wt + hf * (32 * PSTR);
    const float* wp = Wt + rg * 4;
    const int hoff = hf * 32 + bg * 8;

    float c0 = 0.f, c1 = 0.f;         // register-resident cell state
    float b1r[4];
#pragma unroll
    for (int q = 0; q < 4; q++) b1r[q] = b1[q * HIDDEN + cbase + jl];

    for (int t = 0; t < T_STEPS; t++) {
        const int p = t & 1;
        const float* h0_old = g_h0buf[p];
        float*       h0_new = g_h0buf[p ^ 1];
        const float* h1_old = g_h1buf[p];
        float*       h1_new = g_h1buf[p ^ 1];

        // prefetch this thread's X0 gate values (DRAM latency hides under GEMM)
        const float* X0t = g_X0 + (size_t)t * G4 * BATCH;
        float x0r[4];
#pragma unroll
        for (int q = 0; q < 4; q++)
            x0r[q] = X0t[(size_t)(q * HIDDEN + cbase + jl) * BATCH + b];

        // ---- layer 0: gates = X0[t] + W0[:, E:E+H] @ h0_old ----
        float2 acc[4][4];
#pragma unroll
        for (int r = 0; r < 4; r++)
#pragma unroll
            for (int j = 0; j < 4; j++) acc[r][j] = make_float2(0.f, 0.f);

        stage_W(W0, EMBED + HIDDEN, EMBED + s * 128, cbase, Wt, pt);
        barp(s);
        gemm128(h0_old + (size_t)(s * 128) * 64 + hoff, wp, acc);
        barp(s);                      // pair done reading Wt -> alias as partials
        write_partial(acc, part, rg, bg);
        __syncthreads();
        {
            const float* pb = dsm + (b >> 5) * (32 * PSTR) + (b & 31);
            float gs[4];
#pragma unroll
            for (int q = 0; q < 4; q++) {
                float v = x0r[q];
#pragma unroll
                for (int ss = 0; ss < 8; ss++)
                    v += pb[ss * TILE_F + (q * 8 + jl) * PSTR];
                gs[q] = v;
            }
            float cn = sigf(gs[1]) * c0 + sigf(gs[0]) * tanhf(gs[2]);
            c0 = cn;
            h0_new[(cbase + jl) * BATCH + b] = sigf(gs[3]) * tanhf(cn);
        }
        __threadfence();              // release own h0_new stores
        __syncthreads();
        if (tid == 0) atomicAdd(&g_cA, 1u);

        // ---- layer 1: gates = b1 + W1 @ [h0_new ; h1_old] ----
        // splits 0-3 (h0_new) wait on A; splits 4-7 (h1_old) start on B.
#pragma unroll
        for (int r = 0; r < 4; r++)
#pragma unroll
            for (int j = 0; j < 4; j++) acc[r][j] = make_float2(0.f, 0.f);

        const float* hsrc;
        if (s < 4) { ctr_wait(&g_cA, (unsigned)(t + 1) * NCTA, s, pt); hsrc = h0_new; }
        else       { ctr_wait(&g_cB, (unsigned)t * NCTA,       s, pt); hsrc = h1_old; }
        const int kb = (s & 3) * 256;
#pragma unroll
        for (int sp = 0; sp < 2; sp++) {
            stage_W(W1, 2 * HIDDEN, s * 256 + sp * 128, cbase, Wt, pt);
            barp(s);
            gemm128(hsrc + (size_t)(kb + sp * 128) * 64 + hoff, wp, acc);
            barp(s);
        }
        write_partial(acc, part, rg, bg);
        __syncthreads();
        {
            const float* pb = dsm + (b >> 5) * (32 * PSTR) + (b & 31);
            float gs[4];
#pragma unroll
            for (int q = 0; q < 4; q++) {
                float v = b1r[q];
#pragma unroll
                for (int ss = 0; ss < 8; ss++)
                    v += pb[ss * TILE_F + (q * 8 + jl) * PSTR];
                gs[q] = v;
            }
            float cn = sigf(gs[1]) * c1 + sigf(gs[0]) * tanhf(gs[2]);
            c1 = cn;
            h1_new[(cbase + jl) * BATCH + b] = sigf(gs[3]) * tanhf(cn);
        }
        __threadfence();
        __syncthreads();
        if (tid == 0) atomicAdd(&g_cB, 1u);
    }
}

// =====================================================================
// Classifier: out[b][c] = bV[c] + sum_j h1[j][b] * V[c][j]
// (final h1 is g_h1buf[0]: last write at t=511 -> buf[(511&1)^1] = 0)
// =====================================================================
__global__ __launch_bounds__(512) void classify(
    const float* __restrict__ V, const float* __restrict__ bV,
    float* __restrict__ out)
{
    __shared__ float red[512];
    const int c  = blockIdx.x;
    const int tid = threadIdx.x;
    const int b  = tid & 63;
    const int sl = tid >> 6;          // j-slice 0..7
    const float* vr = V + (size_t)c * HIDDEN + sl * 128;
    const float* hp = g_h1buf[0] + (size_t)sl * 128 * BATCH + b;
    float a = 0.f;
#pragma unroll 8
    for (int j = 0; j < 128; j++) a += hp[j * BATCH] * vr[j];
    red[tid] = a;
    __syncthreads();
    if (tid < 64) {
        float ssum = bV[c];
#pragma unroll
        for (int k = 0; k < 8; k++) ssum += red[k * 64 + tid];
        out[tid * NCLS + c] = ssum;
    }
}

__global__ void zero_state()
{
    int i = blockIdx.x * 1024 + threadIdx.x;      // 64 x 1024 = 65536
    g_h0buf[0][i] = 0.f; g_h0buf[1][i] = 0.f;
    g_h1buf[0][i] = 0.f; g_h1buf[1][i] = 0.f;
    if (i == 0) { g_cA = 0u; g_cB = 0u; }
}

// =====================================================================
extern "C" void kernel_launch(void* const* d_in, const int* in_sizes, int n_in,
                              void* d_out, int out_size)
{
    (void)in_sizes; (void)n_in; (void)out_size;
    const int*   x   = (const int*)d_in[0];
    const float* emb = (const float*)d_in[1];
    const float* W0  = (const float*)d_in[2];
    const float* b0  = (const float*)d_in[3];
    const float* W1  = (const float*)d_in[4];
    const float* b1  = (const float*)d_in[5];
    const float* V   = (const float*)d_in[6];
    const float* bV  = (const float*)d_in[7];
    float* out = (float*)d_out;

    cudaFuncSetAttribute(lstm_persistent,
                         cudaFuncAttributeMaxDynamicSharedMemorySize, SMEM_BYTES);

    zero_state<<<64, 1024>>>();
    precompute_x0<<<dim3(T_STEPS, 64), 128>>>(x, emb, W0, b0);
    lstm_persistent<<<NCTA, 512, SMEM_BYTES>>>(W0, W1, b1);
    classify<<<NCLS, BATCH * 8>>>(V, bV, out);
}